// round 7
// baseline (speedup 1.0000x reference)
#include <cuda_runtime.h>
#include <stdint.h>

// CRY gate, DIM=2, N=24, C=0 (bit 23), T=1 (bit 22), J-1=0, K-1=1, B=2.
// x_real/x_imag: (D=2^24, B=2) float32 row-major; out: (2, D, B) float32.
//
// f4 index v in [0, 2^23) per plane; bit22 = control, bit21 = target.
//   control=0 (v < 2^22): identity copy.
//   control=1: pair (v, v+2^21) rotated by [[c,-s],[-s,c]],
//              c=cos(theta/2), s=sin(theta/2), same for real & imag planes.
//
// R5: R1 structure but each thread owns TWO CONSECUTIVE f4 slots (32B
// contiguous per thread, 1KB contiguous per warp per stream) to lengthen
// DRAM bursts per stream. Same one-shot oversubscribed launch as R1.

static constexpr uint32_t N_F4_PER_PLANE = 1u << 23; // D*B/4
static constexpr uint32_t COPY_F4        = 1u << 22; // control=0 region (per plane)
static constexpr uint32_t PAIR_F4        = 1u << 21; // control=1,target=0 region
static constexpr uint32_t COPY_T         = COPY_F4 / 2;            // 2^21 copy threads
static constexpr uint32_t PAIR_T         = PAIR_F4 / 2;            // 2^20 pair threads
static constexpr uint32_t TOTAL_THREADS  = COPY_T + PAIR_T;        // 3,145,728

__global__ void __launch_bounds__(256)
cry_kernel(const float4* __restrict__ xr,
           const float4* __restrict__ xi,
           const float*  __restrict__ angle,
           float4* __restrict__ outr,
           float4* __restrict__ outi)
{
    uint32_t tid = blockIdx.x * blockDim.x + threadIdx.x;
    if (tid >= TOTAL_THREADS) return;

    if (tid < COPY_T) {
        // control = 0: copy two consecutive f4 slots in both planes
        uint32_t a = tid * 2;
        float4 r0 = xr[a], r1 = xr[a + 1];
        float4 i0 = xi[a], i1 = xi[a + 1];
        outr[a] = r0; outr[a + 1] = r1;
        outi[a] = i0; outi[a + 1] = i1;
    } else {
        // control = 1: two consecutive target=0 slots + their partners
        uint32_t p  = tid - COPY_T;          // [0, 2^20)
        uint32_t v0 = COPY_F4 + p * 2;       // target=0, even slot
        uint32_t v1 = v0 + PAIR_F4;          // target=1 partner

        float s, c;
        sincosf(angle[0] * 0.5f, &s, &c);

        // slot 0
        float4 ra0 = xr[v0],     rb0 = xr[v1];
        float4 ia0 = xi[v0],     ib0 = xi[v1];
        // slot 1 (consecutive)
        float4 ra1 = xr[v0 + 1], rb1 = xr[v1 + 1];
        float4 ia1 = xi[v0 + 1], ib1 = xi[v1 + 1];

        float4 oa, ob;
        #define ROT(a_, b_, oa_, ob_)                                  \
            oa_.x =  c * a_.x - s * b_.x;  ob_.x = -s * a_.x + c * b_.x; \
            oa_.y =  c * a_.y - s * b_.y;  ob_.y = -s * a_.y + c * b_.y; \
            oa_.z =  c * a_.z - s * b_.z;  ob_.z = -s * a_.z + c * b_.z; \
            oa_.w =  c * a_.w - s * b_.w;  ob_.w = -s * a_.w + c * b_.w;

        ROT(ra0, rb0, oa, ob); outr[v0]     = oa; outr[v1]     = ob;
        ROT(ra1, rb1, oa, ob); outr[v0 + 1] = oa; outr[v1 + 1] = ob;
        ROT(ia0, ib0, oa, ob); outi[v0]     = oa; outi[v1]     = ob;
        ROT(ia1, ib1, oa, ob); outi[v0 + 1] = oa; outi[v1 + 1] = ob;
        #undef ROT
    }
}

extern "C" void kernel_launch(void* const* d_in, const int* in_sizes, int n_in,
                              void* d_out, int out_size)
{
    const float4* xr    = (const float4*)d_in[0];
    const float4* xi    = (const float4*)d_in[1];
    const float*  angle = (const float*)d_in[2];

    float4* outr = (float4*)d_out;
    float4* outi = outr + N_F4_PER_PLANE;

    const int threads = 256;
    const int blocks  = (int)((TOTAL_THREADS + threads - 1) / threads); // 12288
    cry_kernel<<<blocks, threads>>>(xr, xi, angle, outr, outi);
}

// round 8
// speedup vs baseline: 1.0511x; 1.0511x over previous
#include <cuda_runtime.h>
#include <stdint.h>

// CRY gate, DIM=2, N=24, C=0 (bit 23), T=1 (bit 22), J-1=0, K-1=1, B=2.
// x_real/x_imag: (D=2^24, B=2) float32 row-major; out: (2, D, B) float32.
//
// float2 units: one f2 = one statevector row (B=2). f2 index v in [0, 2^24).
//   bit23 = control, bit22 = target.
//   control=0 (v < 2^23): identity copy.
//   control=1: pair (v, v+2^22) rotated by [[c,-s],[-s,c]],
//              c=cos(theta/2), s=sin(theta/2), same for real & imag planes.
//
// R6: maximum thread count — one float2 per thread, 12.58M threads, following
// the measured trend (more threads / less work per thread -> higher DRAM busy).

static constexpr uint32_t N_F2_PER_PLANE = 1u << 24; // D*B/2
static constexpr uint32_t COPY_F2        = 1u << 23; // control=0 region (per plane)
static constexpr uint32_t PAIR_F2        = 1u << 22; // control=1,target=0 region
static constexpr uint32_t TOTAL_THREADS  = COPY_F2 + PAIR_F2; // 12,582,912

__global__ void __launch_bounds__(256)
cry_kernel(const float2* __restrict__ xr,
           const float2* __restrict__ xi,
           const float*  __restrict__ angle,
           float2* __restrict__ outr,
           float2* __restrict__ outi)
{
    uint32_t tid = blockIdx.x * blockDim.x + threadIdx.x;
    if (tid >= TOTAL_THREADS) return;

    if (tid < COPY_F2) {
        // control = 0: identity copy
        float2 r = xr[tid];
        float2 i = xi[tid];
        outr[tid] = r;
        outi[tid] = i;
    } else {
        // control = 1: tid owns the target=0 member; partner at +2^22 f2
        uint32_t v0 = tid;            // in [2^23, 2^23 + 2^22)
        uint32_t v1 = tid + PAIR_F2;  // target=1 partner

        float s, c;
        sincosf(angle[0] * 0.5f, &s, &c);

        float2 r0 = xr[v0], r1 = xr[v1];
        float2 i0 = xi[v0], i1 = xi[v1];

        float2 or0, or1, oi0, oi1;
        or0.x =  c * r0.x - s * r1.x;  or1.x = -s * r0.x + c * r1.x;
        or0.y =  c * r0.y - s * r1.y;  or1.y = -s * r0.y + c * r1.y;
        oi0.x =  c * i0.x - s * i1.x;  oi1.x = -s * i0.x + c * i1.x;
        oi0.y =  c * i0.y - s * i1.y;  oi1.y = -s * i0.y + c * i1.y;

        outr[v0] = or0; outr[v1] = or1;
        outi[v0] = oi0; outi[v1] = oi1;
    }
}

extern "C" void kernel_launch(void* const* d_in, const int* in_sizes, int n_in,
                              void* d_out, int out_size)
{
    const float2* xr    = (const float2*)d_in[0];
    const float2* xi    = (const float2*)d_in[1];
    const float*  angle = (const float*)d_in[2];

    float2* outr = (float2*)d_out;
    float2* outi = outr + N_F2_PER_PLANE;

    const int threads = 256;
    const int blocks  = (int)((TOTAL_THREADS + threads - 1) / threads); // 49152
    cry_kernel<<<blocks, threads>>>(xr, xi, angle, outr, outi);
}

// round 9
// speedup vs baseline: 1.0597x; 1.0082x over previous
#include <cuda_runtime.h>
#include <stdint.h>

// CRY gate, DIM=2, N=24, C=0 (bit 23), T=1 (bit 22), J-1=0, K-1=1, B=2.
// x_real/x_imag: (D=2^24, B=2) float32 row-major; out: (2, D, B) float32.
//
// f4 index v in [0, 2^23) per plane; bit22 = control, bit21 = target.
//   control=0 (v < 2^22): identity copy.
//   control=1: pair (v, v+2^21) rotated by [[c,-s],[-s,c]],
//              c=cos(theta/2), s=sin(theta/2), same for real & imag planes.
//
// R7: exact R1 structure (measured optimum: 128-bit accesses, one f4 slot
// per thread, fully oversubscribed one-shot grid) with block=128 for finer
// CTA scheduling granularity / smoother wave tail.

static constexpr uint32_t N_F4_PER_PLANE = 1u << 23; // D*B/4
static constexpr uint32_t COPY_F4        = 1u << 22; // control=0 region (per plane)
static constexpr uint32_t PAIR_F4        = 1u << 21; // control=1,target=0 region
static constexpr uint32_t TOTAL_THREADS  = COPY_F4 + PAIR_F4; // 6,291,456

__global__ void __launch_bounds__(128)
cry_kernel(const float4* __restrict__ xr,
           const float4* __restrict__ xi,
           const float*  __restrict__ angle,
           float4* __restrict__ outr,
           float4* __restrict__ outi)
{
    uint32_t tid = blockIdx.x * blockDim.x + threadIdx.x;
    if (tid >= TOTAL_THREADS) return;

    if (tid < COPY_F4) {
        // control = 0: identity copy
        float4 r = xr[tid];
        float4 i = xi[tid];
        outr[tid] = r;
        outi[tid] = i;
    } else {
        // control = 1: tid owns the target=0 member; partner at +2^21 f4
        uint32_t v0 = tid;             // in [2^22, 2^22 + 2^21)
        uint32_t v1 = tid + PAIR_F4;   // target=1 partner (+2^22 rows)

        float s, c;
        sincosf(angle[0] * 0.5f, &s, &c);

        float4 r0 = xr[v0], r1 = xr[v1];
        float4 i0 = xi[v0], i1 = xi[v1];

        float4 or0, or1, oi0, oi1;
        or0.x =  c * r0.x - s * r1.x;  or1.x = -s * r0.x + c * r1.x;
        or0.y =  c * r0.y - s * r1.y;  or1.y = -s * r0.y + c * r1.y;
        or0.z =  c * r0.z - s * r1.z;  or1.z = -s * r0.z + c * r1.z;
        or0.w =  c * r0.w - s * r1.w;  or1.w = -s * r0.w + c * r1.w;

        oi0.x =  c * i0.x - s * i1.x;  oi1.x = -s * i0.x + c * i1.x;
        oi0.y =  c * i0.y - s * i1.y;  oi1.y = -s * i0.y + c * i1.y;
        oi0.z =  c * i0.z - s * i1.z;  oi1.z = -s * i0.z + c * i1.z;
        oi0.w =  c * i0.w - s * i1.w;  oi1.w = -s * i0.w + c * i1.w;

        outr[v0] = or0; outr[v1] = or1;
        outi[v0] = oi0; outi[v1] = oi1;
    }
}

extern "C" void kernel_launch(void* const* d_in, const int* in_sizes, int n_in,
                              void* d_out, int out_size)
{
    const float4* xr    = (const float4*)d_in[0];
    const float4* xi    = (const float4*)d_in[1];
    const float*  angle = (const float*)d_in[2];

    float4* outr = (float4*)d_out;
    float4* outi = outr + N_F4_PER_PLANE;

    const int threads = 128;
    const int blocks  = (int)((TOTAL_THREADS + threads - 1) / threads); // 49152
    cry_kernel<<<blocks, threads>>>(xr, xi, angle, outr, outi);
}